// round 13
// baseline (speedup 1.0000x reference)
#include <cuda_runtime.h>
#include <cuda_fp16.h>

// Problem constants (fixed-shape problem)
#define NN   50000
#define EE   1600000
#define KCH  5
#define H1D  32
#define H2D  16
#define PD   12
#define NB   49   // ceil(NN/1024)
#define GEMM_BLOCKS 296

// ---------------- scratch (static device globals; no allocation) -------------
__device__ int     g_is64;
__device__ float   g_deg[NN];
__device__ float   g_dis[NN];       // deg^-1/2   (0 if deg<=0)
__device__ float   g_d2 [NN];       // deg^-1     (dis^2)
__device__ float   g_s  [NN];       // deg^+1/2   (0 if deg<=0) : T_k = s * U_k
__device__ int     g_cnt[NN];       // in-degree counts (keyed by col)
__device__ int     g_cur[NN];       // CSR fill cursors
__device__ int     g_off[NN + 1];   // CSR offsets keyed by col (destination)
__device__ int     g_bsum[NB];      // per-block count sums for the scan
__device__ int2    g_edge[EE];      // CSR: {src row, float bits of RAW w} per edge
// fp16 node-feature buffers hold U_k = dis .* T_k ; one row = 32 halves = 64B
__device__ __half2 g_U0 [NN * 16];  // dis .* x
__device__ __half2 g_T1h[NN * 16];
__device__ __half2 g_T2h[NN * 16];
__device__ __half2 g_T3h[NN * 16];
__device__ __half2 g_T4h[NN * 16];
__device__ __half2 g_h1h[NN * 16];  // dis .* h1  (cell-2 U0)

// ---------------- packed f32x2 FMA (Blackwell FFMA2) ----------------
__device__ __forceinline__ float2 ffma2(float s, float2 b, float2 c) {
    unsigned lo, hi;
    unsigned su = __float_as_uint(s);
    unsigned bx = __float_as_uint(b.x), by = __float_as_uint(b.y);
    unsigned cx = __float_as_uint(c.x), cy = __float_as_uint(c.y);
    asm("{\n\t"
        ".reg .b64 A,B,C,D;\n\t"
        "mov.b64 A, {%2,%2};\n\t"
        "mov.b64 B, {%3,%4};\n\t"
        "mov.b64 C, {%5,%6};\n\t"
        "fma.rn.f32x2 D, A, B, C;\n\t"
        "mov.b64 {%0,%1}, D;\n\t"
        "}"
        : "=r"(lo), "=r"(hi)
        : "r"(su), "r"(bx), "r"(by), "r"(cx), "r"(cy));
    return make_float2(__uint_as_float(lo), __uint_as_float(hi));
}

// ---------------- init: zero accumulators + dtype detection ----------------
// If edge_index is int64 (little-endian), every odd int32 word is 0 (ids < 50000).
__global__ void k_init(const int* __restrict__ ei) {
    int i = blockIdx.x * blockDim.x + threadIdx.x;
    if (i < NN) { g_deg[i] = 0.f; g_cnt[i] = 0; }
    if (i == 0) g_off[NN] = EE;
    if (blockIdx.x == 0 && threadIdx.x < 32) {
        int nz = ei[2 * threadIdx.x + 1] | ei[2 * (threadIdx.x + 32) + 1];
        unsigned m = __ballot_sync(0xffffffffu, nz != 0);
        if (threadIdx.x == 0) g_is64 = (m == 0) ? 1 : 0;
    }
}

// Degree (keyed by row) and in-degree counts (keyed by col).
__global__ void k_conv(const int* __restrict__ ei, const float* __restrict__ w) {
    int e = blockIdx.x * blockDim.x + threadIdx.x;
    if (e >= EE) return;
    int r, c;
    if (g_is64) { r = ei[2 * e]; c = ei[2 * (EE + e)]; }
    else        { r = ei[e];     c = ei[EE + e];       }
    atomicAdd(&g_deg[r], w[e]);
    atomicAdd(&g_cnt[c], 1);
}

// Scan stage A: per-block count sums + derived degree scalars.
__global__ void k_scanA() {
    __shared__ int sw[32];
    int t = threadIdx.x, lane = t & 31, wid = t >> 5;
    int idx = blockIdx.x * 1024 + t;
    int cnt = (idx < NN) ? g_cnt[idx] : 0;
    if (idx < NN) {
        float d = g_deg[idx];
        float di = d > 0.f ? rsqrtf(d) : 0.f;
        g_dis[idx] = di;
        g_d2[idx]  = di * di;
        g_s[idx]   = d > 0.f ? sqrtf(d) : 0.f;
    }
    int v = cnt;
#pragma unroll
    for (int o = 16; o; o >>= 1) v += __shfl_down_sync(0xffffffffu, v, o);
    if (lane == 0) sw[wid] = v;
    __syncthreads();
    if (wid == 0) {
        int x = sw[lane];
#pragma unroll
        for (int o = 16; o; o >>= 1) x += __shfl_down_sync(0xffffffffu, x, o);
        if (lane == 0) g_bsum[blockIdx.x] = x;
    }
}

// Scan stage C: block-local exclusive scan + base from preceding block sums.
__global__ void k_scanC() {
    __shared__ int s_ws[32];
    __shared__ int s_base;
    int b = blockIdx.x, t = threadIdx.x, lane = t & 31, wid = t >> 5;
    if (wid == 0) {
        int v = 0;
        if (lane < b)      v  = g_bsum[lane];
        if (lane + 32 < b) v += g_bsum[lane + 32];
#pragma unroll
        for (int o = 16; o; o >>= 1) v += __shfl_down_sync(0xffffffffu, v, o);
        if (lane == 0) s_base = v;
    }
    int idx = b * 1024 + t;
    int cnt = (idx < NN) ? g_cnt[idx] : 0;
    int v = cnt;
#pragma unroll
    for (int o = 1; o < 32; o <<= 1) {
        int u = __shfl_up_sync(0xffffffffu, v, o);
        if (lane >= o) v += u;
    }
    if (lane == 31) s_ws[wid] = v;
    __syncthreads();
    if (wid == 0) {
        int w = s_ws[lane];
#pragma unroll
        for (int o = 1; o < 32; o <<= 1) {
            int u = __shfl_up_sync(0xffffffffu, w, o);
            if (lane >= o) w += u;
        }
        s_ws[lane] = w;
    }
    __syncthreads();
    int excl = v - cnt + (wid ? s_ws[wid - 1] : 0) + s_base;
    if (idx < NN) { g_off[idx] = excl; g_cur[idx] = excl; }
}

// Prescale: U0 = dis .* x, fp16.
__global__ void k_prescale(const float* __restrict__ x) {
    int i = blockIdx.x * blockDim.x + threadIdx.x;
    if (i >= NN * 16) return;
    float d = g_dis[i >> 4];
    float2 v = ((const float2*)x)[i];
    g_U0[i] = __floats2half2_rn(d * v.x, d * v.y);
}

// Fill CSR: {src, RAW weight} scattered by col (no dis gathers — normalization
// is folded into the recurrence via per-destination d2 and per-row s).
__global__ void k_fill(const int* __restrict__ ei, const float* __restrict__ w) {
    int e = blockIdx.x * blockDim.x + threadIdx.x;
    if (e >= EE) return;
    int r, c;
    if (g_is64) { r = ei[2 * e]; c = ei[2 * (EE + e)]; }
    else        { r = ei[e];     c = ei[EE + e];       }
    int pos = atomicAdd(&g_cur[c], 1);
    g_edge[pos] = make_int2(r, __float_as_int(w[e]));
}

// Pull-mode fp16 spmm on rescaled basis:
//   Uout[c] = alpha * d2[c] * sum_e w[e]*Uin[src] + beta * Uprev[c]
// (alpha = -1 for pass 1, -2 afterwards; beta = 0 / -1).
// Warp per node; half-warp covers a 64B row, two edges per LDG instruction.
__global__ void k_spmm16(const __half2* __restrict__ Tin, const __half2* __restrict__ Tprev,
                         __half2* __restrict__ Tout, float alpha, float beta)
{
    int gw = (blockIdx.x * blockDim.x + threadIdx.x) >> 5;
    if (gw >= NN) return;
    int lane = threadIdx.x & 31;
    int h = lane >> 4, l = lane & 15;
    int s = g_off[gw], e = g_off[gw + 1];
    float am = alpha * g_d2[gw];
    float accx = 0.f, accy = 0.f;
    int j = s;
    for (; j + 8 <= e; j += 8) {
        int2 e0 = __ldg(&g_edge[j + h]);
        int2 e1 = __ldg(&g_edge[j + 2 + h]);
        int2 e2 = __ldg(&g_edge[j + 4 + h]);
        int2 e3 = __ldg(&g_edge[j + 6 + h]);
        float2 v0 = __half22float2(__ldg(&Tin[(size_t)e0.x * 16 + l]));
        float2 v1 = __half22float2(__ldg(&Tin[(size_t)e1.x * 16 + l]));
        float2 v2 = __half22float2(__ldg(&Tin[(size_t)e2.x * 16 + l]));
        float2 v3 = __half22float2(__ldg(&Tin[(size_t)e3.x * 16 + l]));
        float w0 = __int_as_float(e0.y), w1 = __int_as_float(e1.y);
        float w2 = __int_as_float(e2.y), w3 = __int_as_float(e3.y);
        accx = fmaf(w0, v0.x, accx); accy = fmaf(w0, v0.y, accy);
        accx = fmaf(w1, v1.x, accx); accy = fmaf(w1, v1.y, accy);
        accx = fmaf(w2, v2.x, accx); accy = fmaf(w2, v2.y, accy);
        accx = fmaf(w3, v3.x, accx); accy = fmaf(w3, v3.y, accy);
    }
    if (j + 4 <= e) {
        int2 ea = __ldg(&g_edge[j + h]);
        int2 eb = __ldg(&g_edge[j + 2 + h]);
        float2 va = __half22float2(__ldg(&Tin[(size_t)ea.x * 16 + l]));
        float2 vb = __half22float2(__ldg(&Tin[(size_t)eb.x * 16 + l]));
        float wa = __int_as_float(ea.y), wb = __int_as_float(eb.y);
        accx = fmaf(wa, va.x, accx); accy = fmaf(wa, va.y, accy);
        accx = fmaf(wb, vb.x, accx); accy = fmaf(wb, vb.y, accy);
        j += 4;
    }
    if (j + 2 <= e) {
        int2 ea = __ldg(&g_edge[j + h]);
        float2 va = __half22float2(__ldg(&Tin[(size_t)ea.x * 16 + l]));
        float wa = __int_as_float(ea.y);
        accx = fmaf(wa, va.x, accx); accy = fmaf(wa, va.y, accy);
        j += 2;
    }
    if (j < e && h == 0) {                      // odd tail: half 0 only
        int2 ea = __ldg(&g_edge[j]);
        float2 va = __half22float2(__ldg(&Tin[(size_t)ea.x * 16 + l]));
        float wa = __int_as_float(ea.y);
        accx = fmaf(wa, va.x, accx); accy = fmaf(wa, va.y, accy);
    }
    accx += __shfl_xor_sync(0xffffffffu, accx, 16);
    accy += __shfl_xor_sync(0xffffffffu, accy, 16);
    if (h == 0) {
        float rx = am * accx, ry = am * accy;
        if (beta != 0.f) {
            float2 tp = __half22float2(Tprev[(size_t)gw * 16 + l]);
            rx = fmaf(beta, tp.x, rx);
            ry = fmaf(beta, tp.y, ry);
        }
        Tout[(size_t)gw * 16 + l] = __floats2half2_rn(rx, ry);
    }
}

// H = 0 GRU path: relu((1 - sigmoid(z)) * tanh(h)), MUFU-based fast math
__device__ __forceinline__ float gruact(float z, float h) {
    float sg = __fdividef(1.f, 1.f + __expf(-z));            // sigmoid
    float th = 1.f - __fdividef(2.f, __expf(2.f * h) + 1.f); // tanh; inf-safe
    float v = (1.f - sg) * th;
    return fmaxf(v, 0.f);
}

// Cell-1 dense combine. Grid-stride over node pairs (weights staged once per block).
// k=0 term uses exact fp32 x; k>=1 terms read U_k and are un-scaled by s[n]
// ONCE after accumulation (row scalar factors out of the GEMM).
// Writes h1h = dis[n] * h1  (the cell-2 U0).
__global__ void k_gemm1(const float* __restrict__ x, const float* __restrict__ Wx1,
                        const float* __restrict__ bx1, const float* __restrict__ bh1)
{
    __shared__ float2 sW[KCH * 32 * 32];    // 40KB: [k][i][lane] -> {wz, wh}
    __shared__ float sbz[32], sbh[32];
    int tid = threadIdx.x;
    for (int i = tid; i < KCH * 32 * 32; i += 256)
        sW[i] = make_float2(Wx1[i], Wx1[2 * KCH * 32 * 32 + i]);  // gates 0 (z), 2 (h)
    if (tid < 32) {
        sbz[tid] = bx1[tid]      + bh1[tid];
        sbh[tid] = bx1[64 + tid] + bh1[64 + tid];
    }
    __syncthreads();
    int warp = tid >> 5, lane = tid & 31;
    int gwarp = blockIdx.x * 8 + warp;
    int totw  = gridDim.x * 8;
    const __half* const Ts[4] = { (const __half*)g_T1h, (const __half*)g_T2h,
                                  (const __half*)g_T3h, (const __half*)g_T4h };
    __half* h1 = (__half*)g_h1h;

    for (int pair = gwarp; 2 * pair < NN; pair += totw) {
        int na = 2 * pair, nb = na + 1;
        float2 accAx = make_float2(sbz[lane], sbh[lane]);   // bias + x-term
        float2 accBx = accAx;
        float2 accAu = make_float2(0.f, 0.f);               // U-terms (scale by s later)
        float2 accBu = accAu;
        // k = 0 (exact x)
        {
            float va = x[(size_t)na * 32 + lane];
            float vb = x[(size_t)nb * 32 + lane];
            const float2* w = &sW[0];
#pragma unroll
            for (int i = 0; i < 32; ++i) {
                float ta = __shfl_sync(0xffffffffu, va, i);
                float tb = __shfl_sync(0xffffffffu, vb, i);
                float2 wi = w[i * 32 + lane];
                accAx = ffma2(ta, wi, accAx);
                accBx = ffma2(tb, wi, accBx);
            }
        }
#pragma unroll
        for (int k = 1; k < KCH; ++k) {
            float va = __half2float(Ts[k - 1][(size_t)na * 32 + lane]);
            float vb = __half2float(Ts[k - 1][(size_t)nb * 32 + lane]);
            const float2* w = &sW[k * 1024];
#pragma unroll
            for (int i = 0; i < 32; ++i) {
                float ta = __shfl_sync(0xffffffffu, va, i);
                float tb = __shfl_sync(0xffffffffu, vb, i);
                float2 wi = w[i * 32 + lane];
                accAu = ffma2(ta, wi, accAu);
                accBu = ffma2(tb, wi, accBu);
            }
        }
        float sa = g_s[na],  sb = g_s[nb];
        float da = g_dis[na], db = g_dis[nb];
        float za = fmaf(sa, accAu.x, accAx.x), ha = fmaf(sa, accAu.y, accAx.y);
        float zb = fmaf(sb, accBu.x, accBx.x), hb = fmaf(sb, accBu.y, accBx.y);
        h1[(size_t)na * 32 + lane] = __float2half_rn(da * gruact(za, ha));
        h1[(size_t)nb * 32 + lane] = __float2half_rn(db * gruact(zb, hb));
    }
}

// Cell-2 dense combine + output projection. Grid-stride over node pairs.
// All 5 inputs are U_k (h1h holds dis.*h1 = U0); un-scale by s[n] once at the end.
__global__ void k_gemm2(const float* __restrict__ Wx2, const float* __restrict__ bx2,
                        const float* __restrict__ bh2, const float* __restrict__ Wl,
                        const float* __restrict__ bl,  float* __restrict__ out)
{
    __shared__ float2 sW[KCH * 32 * 16];    // 10KB: [k][i][jj] -> {wz, wh}
    __shared__ float sbz[16], sbh[16], sWl[256], sbl2[12];
    int tid = threadIdx.x;
    for (int i = tid; i < KCH * 32 * 16; i += 256)
        sW[i] = make_float2(Wx2[i], Wx2[2 * KCH * 32 * 16 + i]);
    sWl[tid] = (tid < PD * H2D) ? Wl[tid] : 0.f;   // pad rows 12..15 with zeros
    if (tid < 16) {
        sbz[tid] = bx2[tid]      + bh2[tid];
        sbh[tid] = bx2[32 + tid] + bh2[32 + tid];
    }
    if (tid >= 240 && tid < 240 + PD) sbl2[tid - 240] = bl[tid - 240];
    __syncthreads();
    int warp = tid >> 5, lane = tid & 31;
    int gwarp = blockIdx.x * 8 + warp;
    int totw  = gridDim.x * 8;
    int sel = lane >> 4, jj = lane & 15;
    const __half* const Ts[5] = { (const __half*)g_h1h, (const __half*)g_T1h,
                                  (const __half*)g_T2h, (const __half*)g_T3h,
                                  (const __half*)g_T4h };

    for (int pair = gwarp; 2 * pair < NN; pair += totw) {
        int na = 2 * pair, nb = na + 1;
        float2 acc = make_float2(0.f, 0.f);
#pragma unroll
        for (int k = 0; k < KCH; ++k) {
            float va = __half2float(Ts[k][(size_t)na * 32 + lane]);
            float vb = __half2float(Ts[k][(size_t)nb * 32 + lane]);
            const float2* w = &sW[k * 512];
#pragma unroll
            for (int i = 0; i < 32; ++i) {
                float ta = __shfl_sync(0xffffffffu, va, i);
                float tb = __shfl_sync(0xffffffffu, vb, i);
                float t = sel ? tb : ta;
                acc = ffma2(t, w[i * 16 + jj], acc);
            }
        }
        float sn = sel ? g_s[nb] : g_s[na];
        float h2 = gruact(fmaf(sn, acc.x, sbz[jj]), fmaf(sn, acc.y, sbh[jj]));

        // out[n, p] = sum_j h2[j] * Wl[p, j] + bl[p]
        float o = 0.f;
#pragma unroll
        for (int j = 0; j < 16; ++j) {
            float hv = __shfl_sync(0xffffffffu, h2, (lane & 16) | j);
            o = fmaf(hv, sWl[jj * 16 + j], o);
        }
        if (jj < PD) {
            int n = sel ? nb : na;
            out[(size_t)n * PD + jj] = o + sbl2[jj];
        }
    }
}

// -------------------------------- launch --------------------------------
extern "C" void kernel_launch(void* const* d_in, const int* in_sizes, int n_in,
                              void* d_out, int out_size)
{
    const float* x   = (const float*)d_in[0];
    const int*   ei  = (const int*)  d_in[1];   // int32 view; dtype auto-detected
    const float* ew  = (const float*)d_in[2];
    const float* Wx1 = (const float*)d_in[3];
    const float* bx1 = (const float*)d_in[4];
    // d_in[5] = Wh1: dead (H=0)
    const float* bh1 = (const float*)d_in[6];
    const float* Wx2 = (const float*)d_in[7];
    const float* bx2 = (const float*)d_in[8];
    // d_in[9] = Wh2: dead (H=0)
    const float* bh2 = (const float*)d_in[10];
    const float* Wl  = (const float*)d_in[11];
    const float* bl  = (const float*)d_in[12];
    float* out = (float*)d_out;

    __half2 *U0, *T1p, *T2p, *T3p, *T4p, *h1p;
    cudaGetSymbolAddress((void**)&U0,  g_U0);
    cudaGetSymbolAddress((void**)&T1p, g_T1h);
    cudaGetSymbolAddress((void**)&T2p, g_T2h);
    cudaGetSymbolAddress((void**)&T3p, g_T3h);
    cudaGetSymbolAddress((void**)&T4p, g_T4h);
    cudaGetSymbolAddress((void**)&h1p, g_h1h);

    const int EB = (EE + 255) / 256;
    const int SB = (NN * 32 + 255) / 256;  // warp-per-node spmm

    // CSR build + rescaled basis prep
    k_init<<<(NN + 255) / 256, 256>>>(ei);
    k_conv<<<EB, 256>>>(ei, ew);
    k_scanA<<<NB, 1024>>>();
    k_scanC<<<NB, 1024>>>();
    k_prescale<<<(NN * 16 + 255) / 256, 256>>>(x);
    k_fill<<<EB, 256>>>(ei, ew);

    // Cell 1: Chebyshev U1..U4 on U0 = dis.*x, then fused gate GEMM + act -> h1
    k_spmm16<<<SB, 256>>>(U0,  U0,  T1p, -1.f,  0.f);
    k_spmm16<<<SB, 256>>>(T1p, U0,  T2p, -2.f, -1.f);
    k_spmm16<<<SB, 256>>>(T2p, T1p, T3p, -2.f, -1.f);
    k_spmm16<<<SB, 256>>>(T3p, T2p, T4p, -2.f, -1.f);
    k_gemm1<<<GEMM_BLOCKS, 256>>>(x, Wx1, bx1, bh1);

    // Cell 2: Chebyshev on U0' = dis.*h1, fused gate GEMM + act + output proj
    k_spmm16<<<SB, 256>>>(h1p, h1p, T1p, -1.f,  0.f);
    k_spmm16<<<SB, 256>>>(T1p, h1p, T2p, -2.f, -1.f);
    k_spmm16<<<SB, 256>>>(T2p, T1p, T3p, -2.f, -1.f);
    k_spmm16<<<SB, 256>>>(T3p, T2p, T4p, -2.f, -1.f);
    k_gemm2<<<GEMM_BLOCKS, 256>>>(Wx2, bx2, bh2, Wl, bl, out);
}

// round 14
// speedup vs baseline: 1.0002x; 1.0002x over previous
#include <cuda_runtime.h>
#include <cuda_fp16.h>

// Problem constants (fixed-shape problem)
#define NN   50000
#define EE   1600000
#define KCH  5
#define H1D  32
#define H2D  16
#define PD   12
#define NB   49   // ceil(NN/1024)
#define GEMM_BLOCKS 296

// ---------------- scratch (static device globals; no allocation) -------------
__device__ int     g_is64;
__device__ float   g_deg[NN];
__device__ float   g_dis[NN];       // deg^-1/2   (0 if deg<=0)
__device__ float   g_d2 [NN];       // deg^-1     (dis^2)
__device__ float   g_s  [NN];       // deg^+1/2   (0 if deg<=0) : T_k = s * U_k
__device__ int     g_cnt[NN];       // in-degree counts (keyed by col)
__device__ int     g_cur[NN];       // CSR fill cursors
__device__ int     g_off[NN + 1];   // CSR offsets keyed by col (destination)
__device__ int     g_bsum[NB];      // per-block count sums for the scan
__device__ int2    g_edge[EE];      // CSR: {src row, float bits of RAW w} per edge
// fp16 node-feature buffers hold U_k = dis .* T_k ; one row = 32 halves = 64B
__device__ __half2 g_U0 [NN * 16];  // dis .* x
__device__ __half2 g_T1h[NN * 16];
__device__ __half2 g_T2h[NN * 16];
__device__ __half2 g_T3h[NN * 16];
__device__ __half2 g_T4h[NN * 16];
__device__ __half2 g_h1h[NN * 16];  // dis .* h1  (cell-2 U0)

// ---------------- packed f32x2 FMA (Blackwell FFMA2) ----------------
__device__ __forceinline__ float2 ffma2(float s, float2 b, float2 c) {
    unsigned lo, hi;
    unsigned su = __float_as_uint(s);
    unsigned bx = __float_as_uint(b.x), by = __float_as_uint(b.y);
    unsigned cx = __float_as_uint(c.x), cy = __float_as_uint(c.y);
    asm("{\n\t"
        ".reg .b64 A,B,C,D;\n\t"
        "mov.b64 A, {%2,%2};\n\t"
        "mov.b64 B, {%3,%4};\n\t"
        "mov.b64 C, {%5,%6};\n\t"
        "fma.rn.f32x2 D, A, B, C;\n\t"
        "mov.b64 {%0,%1}, D;\n\t"
        "}"
        : "=r"(lo), "=r"(hi)
        : "r"(su), "r"(bx), "r"(by), "r"(cx), "r"(cy));
    return make_float2(__uint_as_float(lo), __uint_as_float(hi));
}

// ---------------- init: zero accumulators + dtype detection ----------------
// If edge_index is int64 (little-endian), every odd int32 word is 0 (ids < 50000).
__global__ void k_init(const int* __restrict__ ei) {
    int i = blockIdx.x * blockDim.x + threadIdx.x;
    if (i < NN) { g_deg[i] = 0.f; g_cnt[i] = 0; }
    if (i == 0) g_off[NN] = EE;
    if (blockIdx.x == 0 && threadIdx.x < 32) {
        int nz = ei[2 * threadIdx.x + 1] | ei[2 * (threadIdx.x + 32) + 1];
        unsigned m = __ballot_sync(0xffffffffu, nz != 0);
        if (threadIdx.x == 0) g_is64 = (m == 0) ? 1 : 0;
    }
}

// Degree (keyed by row) and in-degree counts (keyed by col).
__global__ void k_conv(const int* __restrict__ ei, const float* __restrict__ w) {
    int e = blockIdx.x * blockDim.x + threadIdx.x;
    if (e >= EE) return;
    int r, c;
    if (g_is64) { r = ei[2 * e]; c = ei[2 * (EE + e)]; }
    else        { r = ei[e];     c = ei[EE + e];       }
    atomicAdd(&g_deg[r], w[e]);
    atomicAdd(&g_cnt[c], 1);
}

// Scan stage A: per-block count sums + derived degree scalars.
__global__ void k_scanA() {
    __shared__ int sw[32];
    int t = threadIdx.x, lane = t & 31, wid = t >> 5;
    int idx = blockIdx.x * 1024 + t;
    int cnt = (idx < NN) ? g_cnt[idx] : 0;
    if (idx < NN) {
        float d = g_deg[idx];
        float di = d > 0.f ? rsqrtf(d) : 0.f;
        g_dis[idx] = di;
        g_d2[idx]  = di * di;
        g_s[idx]   = d > 0.f ? sqrtf(d) : 0.f;
    }
    int v = cnt;
#pragma unroll
    for (int o = 16; o; o >>= 1) v += __shfl_down_sync(0xffffffffu, v, o);
    if (lane == 0) sw[wid] = v;
    __syncthreads();
    if (wid == 0) {
        int x = sw[lane];
#pragma unroll
        for (int o = 16; o; o >>= 1) x += __shfl_down_sync(0xffffffffu, x, o);
        if (lane == 0) g_bsum[blockIdx.x] = x;
    }
}

// Scan stage C: block-local exclusive scan + base from preceding block sums.
__global__ void k_scanC() {
    __shared__ int s_ws[32];
    __shared__ int s_base;
    int b = blockIdx.x, t = threadIdx.x, lane = t & 31, wid = t >> 5;
    if (wid == 0) {
        int v = 0;
        if (lane < b)      v  = g_bsum[lane];
        if (lane + 32 < b) v += g_bsum[lane + 32];
#pragma unroll
        for (int o = 16; o; o >>= 1) v += __shfl_down_sync(0xffffffffu, v, o);
        if (lane == 0) s_base = v;
    }
    int idx = b * 1024 + t;
    int cnt = (idx < NN) ? g_cnt[idx] : 0;
    int v = cnt;
#pragma unroll
    for (int o = 1; o < 32; o <<= 1) {
        int u = __shfl_up_sync(0xffffffffu, v, o);
        if (lane >= o) v += u;
    }
    if (lane == 31) s_ws[wid] = v;
    __syncthreads();
    if (wid == 0) {
        int w = s_ws[lane];
#pragma unroll
        for (int o = 1; o < 32; o <<= 1) {
            int u = __shfl_up_sync(0xffffffffu, w, o);
            if (lane >= o) w += u;
        }
        s_ws[lane] = w;
    }
    __syncthreads();
    int excl = v - cnt + (wid ? s_ws[wid - 1] : 0) + s_base;
    if (idx < NN) { g_off[idx] = excl; g_cur[idx] = excl; }
}

// Prescale: U0 = dis .* x, fp16.
__global__ void k_prescale(const float* __restrict__ x) {
    int i = blockIdx.x * blockDim.x + threadIdx.x;
    if (i >= NN * 16) return;
    float d = g_dis[i >> 4];
    float2 v = ((const float2*)x)[i];
    g_U0[i] = __floats2half2_rn(d * v.x, d * v.y);
}

// Fill CSR: {src, RAW weight} scattered by col (no dis gathers — normalization
// is folded into the recurrence via per-destination d2 and per-row s).
__global__ void k_fill(const int* __restrict__ ei, const float* __restrict__ w) {
    int e = blockIdx.x * blockDim.x + threadIdx.x;
    if (e >= EE) return;
    int r, c;
    if (g_is64) { r = ei[2 * e]; c = ei[2 * (EE + e)]; }
    else        { r = ei[e];     c = ei[EE + e];       }
    int pos = atomicAdd(&g_cur[c], 1);
    g_edge[pos] = make_int2(r, __float_as_int(w[e]));
}

// Pull-mode fp16 spmm on rescaled basis:
//   Uout[c] = alpha * d2[c] * sum_e w[e]*Uin[src] + beta * Uprev[c]
// (alpha = -1 for pass 1, -2 afterwards; beta = 0 / -1).
// Warp per node; half-warp covers a 64B row, two edges per LDG instruction.
__global__ void k_spmm16(const __half2* __restrict__ Tin, const __half2* __restrict__ Tprev,
                         __half2* __restrict__ Tout, float alpha, float beta)
{
    int gw = (blockIdx.x * blockDim.x + threadIdx.x) >> 5;
    if (gw >= NN) return;
    int lane = threadIdx.x & 31;
    int h = lane >> 4, l = lane & 15;
    int s = g_off[gw], e = g_off[gw + 1];
    float am = alpha * g_d2[gw];
    float accx = 0.f, accy = 0.f;
    int j = s;
    for (; j + 8 <= e; j += 8) {
        int2 e0 = __ldg(&g_edge[j + h]);
        int2 e1 = __ldg(&g_edge[j + 2 + h]);
        int2 e2 = __ldg(&g_edge[j + 4 + h]);
        int2 e3 = __ldg(&g_edge[j + 6 + h]);
        float2 v0 = __half22float2(__ldg(&Tin[(size_t)e0.x * 16 + l]));
        float2 v1 = __half22float2(__ldg(&Tin[(size_t)e1.x * 16 + l]));
        float2 v2 = __half22float2(__ldg(&Tin[(size_t)e2.x * 16 + l]));
        float2 v3 = __half22float2(__ldg(&Tin[(size_t)e3.x * 16 + l]));
        float w0 = __int_as_float(e0.y), w1 = __int_as_float(e1.y);
        float w2 = __int_as_float(e2.y), w3 = __int_as_float(e3.y);
        accx = fmaf(w0, v0.x, accx); accy = fmaf(w0, v0.y, accy);
        accx = fmaf(w1, v1.x, accx); accy = fmaf(w1, v1.y, accy);
        accx = fmaf(w2, v2.x, accx); accy = fmaf(w2, v2.y, accy);
        accx = fmaf(w3, v3.x, accx); accy = fmaf(w3, v3.y, accy);
    }
    if (j + 4 <= e) {
        int2 ea = __ldg(&g_edge[j + h]);
        int2 eb = __ldg(&g_edge[j + 2 + h]);
        float2 va = __half22float2(__ldg(&Tin[(size_t)ea.x * 16 + l]));
        float2 vb = __half22float2(__ldg(&Tin[(size_t)eb.x * 16 + l]));
        float wa = __int_as_float(ea.y), wb = __int_as_float(eb.y);
        accx = fmaf(wa, va.x, accx); accy = fmaf(wa, va.y, accy);
        accx = fmaf(wb, vb.x, accx); accy = fmaf(wb, vb.y, accy);
        j += 4;
    }
    if (j + 2 <= e) {
        int2 ea = __ldg(&g_edge[j + h]);
        float2 va = __half22float2(__ldg(&Tin[(size_t)ea.x * 16 + l]));
        float wa = __int_as_float(ea.y);
        accx = fmaf(wa, va.x, accx); accy = fmaf(wa, va.y, accy);
        j += 2;
    }
    if (j < e && h == 0) {                      // odd tail: half 0 only
        int2 ea = __ldg(&g_edge[j]);
        float2 va = __half22float2(__ldg(&Tin[(size_t)ea.x * 16 + l]));
        float wa = __int_as_float(ea.y);
        accx = fmaf(wa, va.x, accx); accy = fmaf(wa, va.y, accy);
    }
    accx += __shfl_xor_sync(0xffffffffu, accx, 16);
    accy += __shfl_xor_sync(0xffffffffu, accy, 16);
    if (h == 0) {
        float rx = am * accx, ry = am * accy;
        if (beta != 0.f) {
            float2 tp = __half22float2(Tprev[(size_t)gw * 16 + l]);
            rx = fmaf(beta, tp.x, rx);
            ry = fmaf(beta, tp.y, ry);
        }
        Tout[(size_t)gw * 16 + l] = __floats2half2_rn(rx, ry);
    }
}

// H = 0 GRU path: relu((1 - sigmoid(z)) * tanh(h)), MUFU-based fast math
__device__ __forceinline__ float gruact(float z, float h) {
    float sg = __fdividef(1.f, 1.f + __expf(-z));            // sigmoid
    float th = 1.f - __fdividef(2.f, __expf(2.f * h) + 1.f); // tanh; inf-safe
    float v = (1.f - sg) * th;
    return fmaxf(v, 0.f);
}

// Cell-1 dense combine. Grid-stride over node pairs (weights staged once per block).
// k=0 term uses exact fp32 x; k>=1 terms read U_k and are un-scaled by s[n]
// ONCE after accumulation (row scalar factors out of the GEMM).
// Writes h1h = dis[n] * h1  (the cell-2 U0).
__global__ void k_gemm1(const float* __restrict__ x, const float* __restrict__ Wx1,
                        const float* __restrict__ bx1, const float* __restrict__ bh1)
{
    __shared__ float2 sW[KCH * 32 * 32];    // 40KB: [k][i][lane] -> {wz, wh}
    __shared__ float sbz[32], sbh[32];
    int tid = threadIdx.x;
    for (int i = tid; i < KCH * 32 * 32; i += 256)
        sW[i] = make_float2(Wx1[i], Wx1[2 * KCH * 32 * 32 + i]);  // gates 0 (z), 2 (h)
    if (tid < 32) {
        sbz[tid] = bx1[tid]      + bh1[tid];
        sbh[tid] = bx1[64 + tid] + bh1[64 + tid];
    }
    __syncthreads();
    int warp = tid >> 5, lane = tid & 31;
    int gwarp = blockIdx.x * 8 + warp;
    int totw  = gridDim.x * 8;
    const __half* const Ts[4] = { (const __half*)g_T1h, (const __half*)g_T2h,
                                  (const __half*)g_T3h, (const __half*)g_T4h };
    __half* h1 = (__half*)g_h1h;

    for (int pair = gwarp; 2 * pair < NN; pair += totw) {
        int na = 2 * pair, nb = na + 1;
        float2 accAx = make_float2(sbz[lane], sbh[lane]);   // bias + x-term
        float2 accBx = accAx;
        float2 accAu = make_float2(0.f, 0.f);               // U-terms (scale by s later)
        float2 accBu = accAu;
        // k = 0 (exact x)
        {
            float va = x[(size_t)na * 32 + lane];
            float vb = x[(size_t)nb * 32 + lane];
            const float2* w = &sW[0];
#pragma unroll
            for (int i = 0; i < 32; ++i) {
                float ta = __shfl_sync(0xffffffffu, va, i);
                float tb = __shfl_sync(0xffffffffu, vb, i);
                float2 wi = w[i * 32 + lane];
                accAx = ffma2(ta, wi, accAx);
                accBx = ffma2(tb, wi, accBx);
            }
        }
#pragma unroll
        for (int k = 1; k < KCH; ++k) {
            float va = __half2float(Ts[k - 1][(size_t)na * 32 + lane]);
            float vb = __half2float(Ts[k - 1][(size_t)nb * 32 + lane]);
            const float2* w = &sW[k * 1024];
#pragma unroll
            for (int i = 0; i < 32; ++i) {
                float ta = __shfl_sync(0xffffffffu, va, i);
                float tb = __shfl_sync(0xffffffffu, vb, i);
                float2 wi = w[i * 32 + lane];
                accAu = ffma2(ta, wi, accAu);
                accBu = ffma2(tb, wi, accBu);
            }
        }
        float sa = g_s[na],  sb = g_s[nb];
        float da = g_dis[na], db = g_dis[nb];
        float za = fmaf(sa, accAu.x, accAx.x), ha = fmaf(sa, accAu.y, accAx.y);
        float zb = fmaf(sb, accBu.x, accBx.x), hb = fmaf(sb, accBu.y, accBx.y);
        h1[(size_t)na * 32 + lane] = __float2half_rn(da * gruact(za, ha));
        h1[(size_t)nb * 32 + lane] = __float2half_rn(db * gruact(zb, hb));
    }
}

// Cell-2 dense combine + output projection. Grid-stride over node pairs.
// All 5 inputs are U_k (h1h holds dis.*h1 = U0); un-scale by s[n] once at the end.
__global__ void k_gemm2(const float* __restrict__ Wx2, const float* __restrict__ bx2,
                        const float* __restrict__ bh2, const float* __restrict__ Wl,
                        const float* __restrict__ bl,  float* __restrict__ out)
{
    __shared__ float2 sW[KCH * 32 * 16];    // 10KB: [k][i][jj] -> {wz, wh}
    __shared__ float sbz[16], sbh[16], sWl[256], sbl2[12];
    int tid = threadIdx.x;
    for (int i = tid; i < KCH * 32 * 16; i += 256)
        sW[i] = make_float2(Wx2[i], Wx2[2 * KCH * 32 * 16 + i]);
    sWl[tid] = (tid < PD * H2D) ? Wl[tid] : 0.f;   // pad rows 12..15 with zeros
    if (tid < 16) {
        sbz[tid] = bx2[tid]      + bh2[tid];
        sbh[tid] = bx2[32 + tid] + bh2[32 + tid];
    }
    if (tid >= 240 && tid < 240 + PD) sbl2[tid - 240] = bl[tid - 240];
    __syncthreads();
    int warp = tid >> 5, lane = tid & 31;
    int gwarp = blockIdx.x * 8 + warp;
    int totw  = gridDim.x * 8;
    int sel = lane >> 4, jj = lane & 15;
    const __half* const Ts[5] = { (const __half*)g_h1h, (const __half*)g_T1h,
                                  (const __half*)g_T2h, (const __half*)g_T3h,
                                  (const __half*)g_T4h };

    for (int pair = gwarp; 2 * pair < NN; pair += totw) {
        int na = 2 * pair, nb = na + 1;
        float2 acc = make_float2(0.f, 0.f);
#pragma unroll
        for (int k = 0; k < KCH; ++k) {
            float va = __half2float(Ts[k][(size_t)na * 32 + lane]);
            float vb = __half2float(Ts[k][(size_t)nb * 32 + lane]);
            const float2* w = &sW[k * 512];
#pragma unroll
            for (int i = 0; i < 32; ++i) {
                float ta = __shfl_sync(0xffffffffu, va, i);
                float tb = __shfl_sync(0xffffffffu, vb, i);
                float t = sel ? tb : ta;
                acc = ffma2(t, w[i * 16 + jj], acc);
            }
        }
        float sn = sel ? g_s[nb] : g_s[na];
        float h2 = gruact(fmaf(sn, acc.x, sbz[jj]), fmaf(sn, acc.y, sbh[jj]));

        // out[n, p] = sum_j h2[j] * Wl[p, j] + bl[p]
        float o = 0.f;
#pragma unroll
        for (int j = 0; j < 16; ++j) {
            float hv = __shfl_sync(0xffffffffu, h2, (lane & 16) | j);
            o = fmaf(hv, sWl[jj * 16 + j], o);
        }
        if (jj < PD) {
            int n = sel ? nb : na;
            out[(size_t)n * PD + jj] = o + sbl2[jj];
        }
    }
}

// -------------------------------- launch --------------------------------
extern "C" void kernel_launch(void* const* d_in, const int* in_sizes, int n_in,
                              void* d_out, int out_size)
{
    const float* x   = (const float*)d_in[0];
    const int*   ei  = (const int*)  d_in[1];   // int32 view; dtype auto-detected
    const float* ew  = (const float*)d_in[2];
    const float* Wx1 = (const float*)d_in[3];
    const float* bx1 = (const float*)d_in[4];
    // d_in[5] = Wh1: dead (H=0)
    const float* bh1 = (const float*)d_in[6];
    const float* Wx2 = (const float*)d_in[7];
    const float* bx2 = (const float*)d_in[8];
    // d_in[9] = Wh2: dead (H=0)
    const float* bh2 = (const float*)d_in[10];
    const float* Wl  = (const float*)d_in[11];
    const float* bl  = (const float*)d_in[12];
    float* out = (float*)d_out;

    __half2 *U0, *T1p, *T2p, *T3p, *T4p, *h1p;
    cudaGetSymbolAddress((void**)&U0,  g_U0);
    cudaGetSymbolAddress((void**)&T1p, g_T1h);
    cudaGetSymbolAddress((void**)&T2p, g_T2h);
    cudaGetSymbolAddress((void**)&T3p, g_T3h);
    cudaGetSymbolAddress((void**)&T4p, g_T4h);
    cudaGetSymbolAddress((void**)&h1p, g_h1h);

    const int EB = (EE + 255) / 256;
    const int SB = (NN * 32 + 255) / 256;  // warp-per-node spmm

    // CSR build + rescaled basis prep
    k_init<<<(NN + 255) / 256, 256>>>(ei);
    k_conv<<<EB, 256>>>(ei, ew);
    k_scanA<<<NB, 1024>>>();
    k_scanC<<<NB, 1024>>>();
    k_prescale<<<(NN * 16 + 255) / 256, 256>>>(x);
    k_fill<<<EB, 256>>>(ei, ew);

    // Cell 1: Chebyshev U1..U4 on U0 = dis.*x, then fused gate GEMM + act -> h1
    k_spmm16<<<SB, 256>>>(U0,  U0,  T1p, -1.f,  0.f);
    k_spmm16<<<SB, 256>>>(T1p, U0,  T2p, -2.f, -1.f);
    k_spmm16<<<SB, 256>>>(T2p, T1p, T3p, -2.f, -1.f);
    k_spmm16<<<SB, 256>>>(T3p, T2p, T4p, -2.f, -1.f);
    k_gemm1<<<GEMM_BLOCKS, 256>>>(x, Wx1, bx1, bh1);

    // Cell 2: Chebyshev on U0' = dis.*h1, fused gate GEMM + act + output proj
    k_spmm16<<<SB, 256>>>(h1p, h1p, T1p, -1.f,  0.f);
    k_spmm16<<<SB, 256>>>(T1p, h1p, T2p, -2.f, -1.f);
    k_spmm16<<<SB, 256>>>(T2p, T1p, T3p, -2.f, -1.f);
    k_spmm16<<<SB, 256>>>(T3p, T2p, T4p, -2.f, -1.f);
    k_gemm2<<<GEMM_BLOCKS, 256>>>(Wx2, bx2, bh2, Wl, bl, out);
}

// round 16
// speedup vs baseline: 1.1004x; 1.1002x over previous
#include <cuda_runtime.h>
#include <cuda_fp16.h>

// Problem constants (fixed-shape problem)
#define NN   50000
#define EE   1600000
#define KCH  5
#define H1D  32
#define H2D  16
#define PD   12
#define NB   49   // ceil(NN/1024)
#define GB1  740   // gemm1 grid: 5 blocks/SM (40KB smem) x 148 SMs
#define GB2  1184  // gemm2 grid: 8 blocks/SM x 148 SMs

// ---------------- scratch (static device globals; no allocation) -------------
__device__ int      g_is64;
__device__ float    g_deg[NN];
__device__ float    g_dis[NN];       // deg^-1/2   (0 if deg<=0)
__device__ float    g_d2 [NN];       // deg^-1     (dis^2)
__device__ float    g_s  [NN];       // deg^+1/2   (0 if deg<=0) : T_k = s * U_k
__device__ int      g_cnt[NN];       // in-degree counts (keyed by col)
__device__ int      g_cur[NN];       // CSR fill cursors
__device__ int      g_off[NN + 1];   // CSR offsets keyed by col (destination)
__device__ int      g_bsum[NB];      // per-block count sums for the scan
__device__ unsigned g_rc[EE];        // cached {row | col<<16} from k_conv
__device__ unsigned short g_wh[EE];  // cached half(w)
__device__ unsigned g_edgeP[EE];     // CSR: {src(16b) | half(w)(16b)} per edge
// fp16 node-feature buffers hold U_k = dis .* T_k ; one row = 32 halves = 64B
__device__ __half2  g_U0 [NN * 16];  // dis .* x
__device__ __half2  g_T1h[NN * 16];
__device__ __half2  g_T2h[NN * 16];
__device__ __half2  g_T3h[NN * 16];
__device__ __half2  g_T4h[NN * 16];
__device__ __half2  g_h1h[NN * 16];  // dis .* h1  (cell-2 U0)

// ---------------- packed f32x2 FMA (Blackwell FFMA2) ----------------
__device__ __forceinline__ float2 ffma2(float s, float2 b, float2 c) {
    unsigned lo, hi;
    unsigned su = __float_as_uint(s);
    unsigned bx = __float_as_uint(b.x), by = __float_as_uint(b.y);
    unsigned cx = __float_as_uint(c.x), cy = __float_as_uint(c.y);
    asm("{\n\t"
        ".reg .b64 A,B,C,D;\n\t"
        "mov.b64 A, {%2,%2};\n\t"
        "mov.b64 B, {%3,%4};\n\t"
        "mov.b64 C, {%5,%6};\n\t"
        "fma.rn.f32x2 D, A, B, C;\n\t"
        "mov.b64 {%0,%1}, D;\n\t"
        "}"
        : "=r"(lo), "=r"(hi)
        : "r"(su), "r"(bx), "r"(by), "r"(cx), "r"(cy));
    return make_float2(__uint_as_float(lo), __uint_as_float(hi));
}

__device__ __forceinline__ float wof(unsigned p) {   // high 16 bits -> fp16 -> f32
    return __half2float(__ushort_as_half((unsigned short)(p >> 16)));
}

// ---------------- init: zero accumulators + dtype detection ----------------
__global__ void k_init(const int* __restrict__ ei) {
    int i = blockIdx.x * blockDim.x + threadIdx.x;
    if (i < NN) { g_deg[i] = 0.f; g_cnt[i] = 0; }
    if (i == 0) g_off[NN] = EE;
    if (blockIdx.x == 0 && threadIdx.x < 32) {
        int nz = ei[2 * threadIdx.x + 1] | ei[2 * (threadIdx.x + 32) + 1];
        unsigned m = __ballot_sync(0xffffffffu, nz != 0);
        if (threadIdx.x == 0) g_is64 = (m == 0) ? 1 : 0;
    }
}

// Degree (keyed by row), counts (keyed by col); cache packed rc + half(w)
// so k_fill never touches edge_index again.
__global__ void k_conv(const int* __restrict__ ei, const float* __restrict__ w) {
    int e = blockIdx.x * blockDim.x + threadIdx.x;
    if (e >= EE) return;
    int r, c;
    if (g_is64) { r = ei[2 * e]; c = ei[2 * (EE + e)]; }
    else        { r = ei[e];     c = ei[EE + e];       }
    float wv = w[e];
    g_rc[e] = (unsigned)r | ((unsigned)c << 16);
    g_wh[e] = __half_as_ushort(__float2half_rn(wv));
    atomicAdd(&g_deg[r], wv);
    atomicAdd(&g_cnt[c], 1);
}

// Scan stage A: per-block count sums + derived degree scalars.
__global__ void k_scanA() {
    __shared__ int sw[32];
    int t = threadIdx.x, lane = t & 31, wid = t >> 5;
    int idx = blockIdx.x * 1024 + t;
    int cnt = (idx < NN) ? g_cnt[idx] : 0;
    if (idx < NN) {
        float d = g_deg[idx];
        float di = d > 0.f ? rsqrtf(d) : 0.f;
        g_dis[idx] = di;
        g_d2[idx]  = di * di;
        g_s[idx]   = d > 0.f ? sqrtf(d) : 0.f;
    }
    int v = cnt;
#pragma unroll
    for (int o = 16; o; o >>= 1) v += __shfl_down_sync(0xffffffffu, v, o);
    if (lane == 0) sw[wid] = v;
    __syncthreads();
    if (wid == 0) {
        int x = sw[lane];
#pragma unroll
        for (int o = 16; o; o >>= 1) x += __shfl_down_sync(0xffffffffu, x, o);
        if (lane == 0) g_bsum[blockIdx.x] = x;
    }
}

// Scan stage C: block-local exclusive scan + base from preceding block sums.
__global__ void k_scanC() {
    __shared__ int s_ws[32];
    __shared__ int s_base;
    int b = blockIdx.x, t = threadIdx.x, lane = t & 31, wid = t >> 5;
    if (wid == 0) {
        int v = 0;
        if (lane < b)      v  = g_bsum[lane];
        if (lane + 32 < b) v += g_bsum[lane + 32];
#pragma unroll
        for (int o = 16; o; o >>= 1) v += __shfl_down_sync(0xffffffffu, v, o);
        if (lane == 0) s_base = v;
    }
    int idx = b * 1024 + t;
    int cnt = (idx < NN) ? g_cnt[idx] : 0;
    int v = cnt;
#pragma unroll
    for (int o = 1; o < 32; o <<= 1) {
        int u = __shfl_up_sync(0xffffffffu, v, o);
        if (lane >= o) v += u;
    }
    if (lane == 31) s_ws[wid] = v;
    __syncthreads();
    if (wid == 0) {
        int w = s_ws[lane];
#pragma unroll
        for (int o = 1; o < 32; o <<= 1) {
            int u = __shfl_up_sync(0xffffffffu, w, o);
            if (lane >= o) w += u;
        }
        s_ws[lane] = w;
    }
    __syncthreads();
    int excl = v - cnt + (wid ? s_ws[wid - 1] : 0) + s_base;
    if (idx < NN) { g_off[idx] = excl; g_cur[idx] = excl; }
}

// Prescale: U0 = dis .* x, fp16.
__global__ void k_prescale(const float* __restrict__ x) {
    int i = blockIdx.x * blockDim.x + threadIdx.x;
    if (i >= NN * 16) return;
    float d = g_dis[i >> 4];
    float2 v = ((const float2*)x)[i];
    g_U0[i] = __floats2half2_rn(d * v.x, d * v.y);
}

// Fill CSR: {src | half(w)<<16} scattered by col, from the cached rc/wh streams.
__global__ void k_fill() {
    int e = blockIdx.x * blockDim.x + threadIdx.x;
    if (e >= EE) return;
    unsigned p = g_rc[e];
    int r = p & 0xFFFFu, c = p >> 16;
    int pos = atomicAdd(&g_cur[c], 1);
    g_edgeP[pos] = (unsigned)r | ((unsigned)g_wh[e] << 16);
}

// Pull-mode fp16 spmm on rescaled basis:
//   Uout[c] = alpha * d2[c] * sum_e w[e]*Uin[src] + beta * Uprev[c]
// Warp per node; QUARTER-warp (8 lanes) covers a 64B row (lane = 8B = 4 halves).
// Vector loads of the edge stream require j aligned: peel scalar edges to
// 4-alignment first (THE round-15 bug: uint4 at (j>>2) reads edges 4*(j>>2),
// not j, whenever j%4 != 0).
__global__ void k_spmm16(const __half2* __restrict__ Tin, const __half2* __restrict__ Tprev,
                         __half2* __restrict__ Tout, float alpha, float beta)
{
    int gw = (blockIdx.x * blockDim.x + threadIdx.x) >> 5;
    if (gw >= NN) return;
    int lane = threadIdx.x & 31;
    int q = lane >> 3, l8 = lane & 7;
    const uint2* Tin8 = (const uint2*)Tin;   // row = 8 x uint2 (64B)
    int s = g_off[gw], e = g_off[gw + 1];
    float am = alpha * g_d2[gw];
    float2 acc0 = make_float2(0.f, 0.f);     // features l8*4 + {0,1}
    float2 acc1 = make_float2(0.f, 0.f);     // features l8*4 + {2,3}
    int j = s;
    // head peel: scalar edges until j % 4 == 0 (quarter q takes edge j+q, masked)
    int mis = j & 3;
    if (mis) {
        int cntp = 4 - mis; if (cntp > e - j) cntp = e - j;
        unsigned p = (q < cntp) ? __ldg(&g_edgeP[j + q]) : 0u;
        int s0 = p & 0xFFFFu;
        uint2 r0 = __ldg(&Tin8[(size_t)s0 * 8 + l8]);
        float w0 = wof(p);                    // p=0 -> w=0: harmless row-0 read
        acc0 = ffma2(w0, __half22float2(*(const __half2*)&r0.x), acc0);
        acc1 = ffma2(w0, __half22float2(*(const __half2*)&r0.y), acc1);
        j += cntp;
    }
    // main: 16 edges / iteration (quarter q handles edges j+4q .. j+4q+3); j%4==0
    for (; j + 16 <= e; j += 16) {
        uint4 ep = __ldg((const uint4*)g_edgeP + (j >> 2) + q);
        int s0 = ep.x & 0xFFFFu, s1 = ep.y & 0xFFFFu;
        int s2 = ep.z & 0xFFFFu, s3 = ep.w & 0xFFFFu;
        uint2 r0 = __ldg(&Tin8[(size_t)s0 * 8 + l8]);
        uint2 r1 = __ldg(&Tin8[(size_t)s1 * 8 + l8]);
        uint2 r2 = __ldg(&Tin8[(size_t)s2 * 8 + l8]);
        uint2 r3 = __ldg(&Tin8[(size_t)s3 * 8 + l8]);
        float w0 = wof(ep.x), w1 = wof(ep.y), w2 = wof(ep.z), w3 = wof(ep.w);
        acc0 = ffma2(w0, __half22float2(*(const __half2*)&r0.x), acc0);
        acc1 = ffma2(w0, __half22float2(*(const __half2*)&r0.y), acc1);
        acc0 = ffma2(w1, __half22float2(*(const __half2*)&r1.x), acc0);
        acc1 = ffma2(w1, __half22float2(*(const __half2*)&r1.y), acc1);
        acc0 = ffma2(w2, __half22float2(*(const __half2*)&r2.x), acc0);
        acc1 = ffma2(w2, __half22float2(*(const __half2*)&r2.y), acc1);
        acc0 = ffma2(w3, __half22float2(*(const __half2*)&r3.x), acc0);
        acc1 = ffma2(w3, __half22float2(*(const __half2*)&r3.y), acc1);
    }
    // mid: 8 edges (quarter q handles edges j+2q, j+2q+1); j%4==0 -> j even
    if (j + 8 <= e) {
        uint2 ep = __ldg((const uint2*)g_edgeP + (j >> 1) + q);
        int s0 = ep.x & 0xFFFFu, s1 = ep.y & 0xFFFFu;
        uint2 r0 = __ldg(&Tin8[(size_t)s0 * 8 + l8]);
        uint2 r1 = __ldg(&Tin8[(size_t)s1 * 8 + l8]);
        float w0 = wof(ep.x), w1 = wof(ep.y);
        acc0 = ffma2(w0, __half22float2(*(const __half2*)&r0.x), acc0);
        acc1 = ffma2(w0, __half22float2(*(const __half2*)&r0.y), acc1);
        acc0 = ffma2(w1, __half22float2(*(const __half2*)&r1.x), acc0);
        acc1 = ffma2(w1, __half22float2(*(const __half2*)&r1.y), acc1);
        j += 8;
    }
    // tail: 4 edges / iteration, masked (p=0 -> w=0, src=0: harmless row-0 read)
    for (; j < e; j += 4) {
        int idx = j + q;
        unsigned p = (idx < e) ? __ldg(&g_edgeP[idx]) : 0u;
        int s0 = p & 0xFFFFu;
        uint2 r0 = __ldg(&Tin8[(size_t)s0 * 8 + l8]);
        float w0 = wof(p);
        acc0 = ffma2(w0, __half22float2(*(const __half2*)&r0.x), acc0);
        acc1 = ffma2(w0, __half22float2(*(const __half2*)&r0.y), acc1);
    }
    // reduce across the 4 quarters (same features live at same l8)
#pragma unroll
    for (int o = 8; o <= 16; o <<= 1) {
        acc0.x += __shfl_xor_sync(0xffffffffu, acc0.x, o);
        acc0.y += __shfl_xor_sync(0xffffffffu, acc0.y, o);
        acc1.x += __shfl_xor_sync(0xffffffffu, acc1.x, o);
        acc1.y += __shfl_xor_sync(0xffffffffu, acc1.y, o);
    }
    if (lane < 8) {
        float2 r0 = make_float2(am * acc0.x, am * acc0.y);
        float2 r1 = make_float2(am * acc1.x, am * acc1.y);
        if (beta != 0.f) {
            uint2 tp = ((const uint2*)Tprev)[(size_t)gw * 8 + lane];
            float2 t0 = __half22float2(*(const __half2*)&tp.x);
            float2 t1 = __half22float2(*(const __half2*)&tp.y);
            r0 = ffma2(beta, t0, r0);
            r1 = ffma2(beta, t1, r1);
        }
        uint2 o2;
        *(__half2*)&o2.x = __floats2half2_rn(r0.x, r0.y);
        *(__half2*)&o2.y = __floats2half2_rn(r1.x, r1.y);
        ((uint2*)Tout)[(size_t)gw * 8 + lane] = o2;
    }
}

// H = 0 GRU path: relu((1 - sigmoid(z)) * tanh(h)), MUFU-based fast math
__device__ __forceinline__ float gruact(float z, float h) {
    float sg = __fdividef(1.f, 1.f + __expf(-z));            // sigmoid
    float th = 1.f - __fdividef(2.f, __expf(2.f * h) + 1.f); // tanh; inf-safe
    float v = (1.f - sg) * th;
    return fmaxf(v, 0.f);
}

// Cell-1 dense combine. Grid-stride over node pairs (weights staged once/block).
// k=0 term uses exact fp32 x; k>=1 terms read U_k, un-scaled by s[n] once at end.
// Writes h1h = dis[n] * h1 (the cell-2 U0).
__global__ void __launch_bounds__(256) k_gemm1(
        const float* __restrict__ x, const float* __restrict__ Wx1,
        const float* __restrict__ bx1, const float* __restrict__ bh1)
{
    __shared__ float2 sW[KCH * 32 * 32];    // 40KB: [k][i][lane] -> {wz, wh}
    __shared__ float sbz[32], sbh[32];
    int tid = threadIdx.x;
    for (int i = tid; i < KCH * 32 * 32; i += 256)
        sW[i] = make_float2(Wx1[i], Wx1[2 * KCH * 32 * 32 + i]);  // gates 0 (z), 2 (h)
    if (tid < 32) {
        sbz[tid] = bx1[tid]      + bh1[tid];
        sbh[tid] = bx1[64 + tid] + bh1[64 + tid];
    }
    __syncthreads();
    int warp = tid >> 5, lane = tid & 31;
    int gwarp = blockIdx.x * 8 + warp;
    int totw  = gridDim.x * 8;
    const __half* const Ts[4] = { (const __half*)g_T1h, (const __half*)g_T2h,
                                  (const __half*)g_T3h, (const __half*)g_T4h };
    __half* h1 = (__half*)g_h1h;

    for (int pair = gwarp; 2 * pair < NN; pair += totw) {
        int na = 2 * pair, nb = na + 1;
        float2 accAx = make_float2(sbz[lane], sbh[lane]);   // bias + x-term
        float2 accBx = accAx;
        float2 accAu = make_float2(0.f, 0.f);               // U-terms (scale by s later)
        float2 accBu = accAu;
        {   // k = 0 (exact x)
            float va = x[(size_t)na * 32 + lane];
            float vb = x[(size_t)nb * 32 + lane];
            const float2* w = &sW[0];
#pragma unroll
            for (int i = 0; i < 32; ++i) {
                float ta = __shfl_sync(0xffffffffu, va, i);
                float tb = __shfl_sync(0xffffffffu, vb, i);
                float2 wi = w[i * 32 + lane];
                accAx = ffma2(ta, wi, accAx);
                accBx = ffma2(tb, wi, accBx);
            }
        }
#pragma unroll
        for (int k = 1; k < KCH; ++k) {
            float va = __half2float(Ts[k - 1][(size_t)na * 32 + lane]);
            float vb = __half2float(Ts[k - 1][(size_t)nb * 32 + lane]);
            const float2* w = &sW[k * 1024];
#pragma unroll
            for (int i = 0; i < 32; ++i) {
                float ta = __shfl_sync(0xffffffffu, va, i);
                float tb = __shfl_sync(0xffffffffu, vb, i);
                float2 wi = w[i * 32 + lane];
                accAu = ffma2(ta, wi, accAu);
                accBu = ffma2(tb, wi, accBu);
            }
        }
        float sa = g_s[na],  sb = g_s[nb];
        float da = g_dis[na], db = g_dis[nb];
        float za = fmaf(sa, accAu.x, accAx.x), ha = fmaf(sa, accAu.y, accAx.y);
        float zb = fmaf(sb, accBu.x, accBx.x), hb = fmaf(sb, accBu.y, accBx.y);
        h1[(size_t)na * 32 + lane] = __float2half_rn(da * gruact(za, ha));
        h1[(size_t)nb * 32 + lane] = __float2half_rn(db * gruact(zb, hb));
    }
}

// Cell-2 dense combine + output projection. Grid-stride over node pairs.
// All 5 inputs are U_k (h1h holds dis.*h1 = U0); un-scale by s[n] once at end.
__global__ void __launch_bounds__(256) k_gemm2(
        const float* __restrict__ Wx2, const float* __restrict__ bx2,
        const float* __restrict__ bh2, const float* __restrict__ Wl,
        const float* __restrict__ bl,  float* __restrict__ out)
{
    __shared__ float2 sW[KCH * 32 * 16];    // 10KB: [k][i][jj] -> {wz, wh}
    __shared__ float sbz[16], sbh[16], sWl[256], sbl2[12];
    int tid = threadIdx.x;
    for (int i = tid; i < KCH * 32 * 16; i += 256)
        sW[i] = make_float2(Wx2[i], Wx2[2 * KCH * 32 * 16 + i]);
    sWl[tid] = (tid < PD * H2D) ? Wl[tid] : 0.f;   // pad rows 12..15 with zeros
    if (tid < 16) {
        sbz[tid] = bx2[tid]      + bh2[tid];
        sbh[tid] = bx2[32 + tid] + bh2[32 + tid];
    }
    if (tid >= 240 && tid < 240 + PD) sbl2[tid - 240] = bl[tid - 240];
    __syncthreads();
    int warp = tid >> 5, lane = tid & 31;
    int gwarp = blockIdx.x * 8 + warp;
    int totw  = gridDim.x * 8;
    int sel = lane >> 4, jj = lane & 15;
    const __half* const Ts[5] = { (const __half*)g_h1h, (const __half*)g_T1h,
                                  (const __half*)g_T2h, (const __half*)g_T3h,
                                  (const __half*)g_T4h };

    for (int pair = gwarp; 2 * pair < NN; pair += totw) {
        int na = 2 * pair, nb = na + 1;
        float2 acc = make_float2(0.f, 0.f);
#pragma unroll
        for (int k = 0; k < KCH; ++k) {
            float va = __half2float(Ts[k][(size_t)na * 32 + lane]);
            float vb = __half2float(Ts[k][(size_t)nb * 32 + lane]);
            const float2* w = &sW[k * 512];
#pragma unroll
            for (int i = 0; i < 32; ++i) {
                float ta = __shfl_sync(0xffffffffu, va, i);
                float tb = __shfl_sync(0xffffffffu, vb, i);
                float t = sel ? tb : ta;
                acc = ffma2(t, w[i * 16 + jj], acc);
            }
        }
        float sn = sel ? g_s[nb] : g_s[na];
        float h2 = gruact(fmaf(sn, acc.x, sbz[jj]), fmaf(sn, acc.y, sbh[jj]));

        float o = 0.f;
#pragma unroll
        for (int j = 0; j < 16; ++j) {
            float hv = __shfl_sync(0xffffffffu, h2, (lane & 16) | j);
            o = fmaf(hv, sWl[jj * 16 + j], o);
        }
        if (jj < PD) {
            int n = sel ? nb : na;
            out[(size_t)n * PD + jj] = o + sbl2[jj];
        }
    }
}

// -------------------------------- launch --------------------------------
extern "C" void kernel_launch(void* const* d_in, const int* in_sizes, int n_in,
                              void* d_out, int out_size)
{
    const float* x   = (const float*)d_in[0];
    const int*   ei  = (const int*)  d_in[1];   // int32 view; dtype auto-detected
    const float* ew  = (const float*)d_in[2];
    const float* Wx1 = (const float*)d_in[3];
    const float* bx1 = (const float*)d_in[4];
    // d_in[5] = Wh1: dead (H=0)
    const float* bh1 = (const float*)d_in[6];
    const float* Wx2 = (const float*)d_in[7];
    const float* bx2 = (const float*)d_in[8];
    // d_in[9] = Wh2: dead (H=0)
    const float* bh2 = (const float*)d_in[10];
    const float* Wl  = (const float*)d_in[11];
    const float* bl  = (const float*)d_in[12];
    float* out = (float*)d_out;

    __half2 *U0, *T1p, *T2p, *T3p, *T4p, *h1p;
    cudaGetSymbolAddress((void**)&U0,  g_U0);
    cudaGetSymbolAddress((void**)&T1p, g_T1h);
    cudaGetSymbolAddress((void**)&T2p, g_T2h);
    cudaGetSymbolAddress((void**)&T3p, g_T3h);
    cudaGetSymbolAddress((void**)&T4p, g_T4h);
    cudaGetSymbolAddress((void**)&h1p, g_h1h);

    const int EB = (EE + 255) / 256;
    const int SB = (NN * 32 + 255) / 256;  // warp-per-node spmm

    // CSR build + rescaled basis prep
    k_init<<<(NN + 255) / 256, 256>>>(ei);
    k_conv<<<EB, 256>>>(ei, ew);
    k_scanA<<<NB, 1024>>>();
    k_scanC<<<NB, 1024>>>();
    k_prescale<<<(NN * 16 + 255) / 256, 256>>>(x);
    k_fill<<<EB, 256>>>();

    // Cell 1: Chebyshev U1..U4 on U0 = dis.*x, then fused gate GEMM + act -> h1
    k_spmm16<<<SB, 256>>>(U0,  U0,  T1p, -1.f,  0.f);
    k_spmm16<<<SB, 256>>>(T1p, U0,  T2p, -2.f, -1.f);
    k_spmm16<<<SB, 256>>>(T2p, T1p, T3p, -2.f, -1.f);
    k_spmm16<<<SB, 256>>>(T3p, T2p, T4p, -2.f, -1.f);
    k_gemm1<<<GB1, 256>>>(x, Wx1, bx1, bh1);

    // Cell 2: Chebyshev on U0' = dis.*h1, fused gate GEMM + act + output proj
    k_spmm16<<<SB, 256>>>(h1p, h1p, T1p, -1.f,  0.f);
    k_spmm16<<<SB, 256>>>(T1p, h1p, T2p, -2.f, -1.f);
    k_spmm16<<<SB, 256>>>(T2p, T1p, T3p, -2.f, -1.f);
    k_spmm16<<<SB, 256>>>(T3p, T2p, T4p, -2.f, -1.f);
    k_gemm2<<<GB2, 256>>>(Wx2, bx2, bh2, Wl, bl, out);
}

// round 17
// speedup vs baseline: 1.3418x; 1.2193x over previous
#include <cuda_runtime.h>
#include <cuda_fp16.h>

// Problem constants (fixed-shape problem)
#define NN   50000
#define EE   1600000
#define KCH  5
#define H1D  32
#define H2D  16
#define PD   12
#define NB   49    // ceil(NN/1024)
#define GB1  296   // gemm1: 2 blocks/SM (40KB smem each), grid-stride
#define GB2  196   // gemm2: covers 1563 groups at 8 warps/block

// ---------------- scratch (static device globals; no allocation) -------------
__device__ int      g_is64;
__device__ float    g_deg[NN];
__device__ float    g_dis[NN];       // deg^-1/2   (0 if deg<=0)
__device__ float    g_d2 [NN];       // deg^-1     (dis^2)
__device__ float    g_s  [NN];       // deg^+1/2   (0 if deg<=0) : T_k = s * U_k
__device__ int      g_cnt[NN];       // in-degree counts (keyed by col)
__device__ int      g_cur[NN];       // CSR fill cursors
__device__ int      g_off[NN + 1];   // CSR offsets keyed by col (destination)
__device__ int      g_bsum[NB];      // per-block count sums for the scan
__device__ uint2    g_rcw[EE];       // cached {src | half(w)<<16, col}
__device__ unsigned g_edgeP[EE];     // CSR: {src(16b) | half(w)(16b)} per edge
// fp16 node-feature buffers hold U_k = dis .* T_k ; one row = 32 halves = 64B
__device__ __half2  g_U0 [NN * 16];  // dis .* x
__device__ __half2  g_T1h[NN * 16];
__device__ __half2  g_T2h[NN * 16];
__device__ __half2  g_T3h[NN * 16];
__device__ __half2  g_T4h[NN * 16];
__device__ __half2  g_h1h[NN * 16];  // dis .* h1  (cell-2 U0)

// ---------------- packed f32x2 FMA (Blackwell FFMA2) ----------------
__device__ __forceinline__ float2 ffma2(float s, float2 b, float2 c) {
    unsigned lo, hi;
    unsigned su = __float_as_uint(s);
    unsigned bx = __float_as_uint(b.x), by = __float_as_uint(b.y);
    unsigned cx = __float_as_uint(c.x), cy = __float_as_uint(c.y);
    asm("{\n\t"
        ".reg .b64 A,B,C,D;\n\t"
        "mov.b64 A, {%2,%2};\n\t"
        "mov.b64 B, {%3,%4};\n\t"
        "mov.b64 C, {%5,%6};\n\t"
        "fma.rn.f32x2 D, A, B, C;\n\t"
        "mov.b64 {%0,%1}, D;\n\t"
        "}"
        : "=r"(lo), "=r"(hi)
        : "r"(su), "r"(bx), "r"(by), "r"(cx), "r"(cy));
    return make_float2(__uint_as_float(lo), __uint_as_float(hi));
}

__device__ __forceinline__ float wof(unsigned p) {   // high 16 bits -> fp16 -> f32
    return __half2float(__ushort_as_half((unsigned short)(p >> 16)));
}

// ---------------- init: zero accumulators + dtype detection ----------------
__global__ void k_init(const int* __restrict__ ei) {
    int i = blockIdx.x * blockDim.x + threadIdx.x;
    if (i < NN) { g_deg[i] = 0.f; g_cnt[i] = 0; }
    if (i == 0) g_off[NN] = EE;
    if (blockIdx.x == 0 && threadIdx.x < 32) {
        int nz = ei[2 * threadIdx.x + 1] | ei[2 * (threadIdx.x + 32) + 1];
        unsigned m = __ballot_sync(0xffffffffu, nz != 0);
        if (threadIdx.x == 0) g_is64 = (m == 0) ? 1 : 0;
    }
}

// Degree (keyed by row), counts (keyed by col); cache the fill-ready payload
// {src | half(w)<<16} plus col in ONE uint2 so k_fill does 1 LDG.64 + 1 STG.32.
__global__ void k_conv(const int* __restrict__ ei, const float* __restrict__ w) {
    int e = blockIdx.x * blockDim.x + threadIdx.x;
    if (e >= EE) return;
    int r, c;
    if (g_is64) { r = ei[2 * e]; c = ei[2 * (EE + e)]; }
    else        { r = ei[e];     c = ei[EE + e];       }
    float wv = w[e];
    unsigned payload = (unsigned)r |
                       ((unsigned)__half_as_ushort(__float2half_rn(wv)) << 16);
    g_rcw[e] = make_uint2(payload, (unsigned)c);
    atomicAdd(&g_deg[r], wv);
    atomicAdd(&g_cnt[c], 1);
}

// Scan stage A: per-block count sums + degree scalars + fused x->U0 prescale.
__global__ void k_scanA(const float* __restrict__ x) {
    __shared__ int sw[32];
    int t = threadIdx.x, lane = t & 31, wid = t >> 5;
    int idx = blockIdx.x * 1024 + t;
    int cnt = (idx < NN) ? g_cnt[idx] : 0;
    if (idx < NN) {
        float d = g_deg[idx];
        float di = d > 0.f ? rsqrtf(d) : 0.f;
        g_dis[idx] = di;
        g_d2[idx]  = di * di;
        g_s[idx]   = d > 0.f ? sqrtf(d) : 0.f;
    }
    int v = cnt;
#pragma unroll
    for (int o = 16; o; o >>= 1) v += __shfl_down_sync(0xffffffffu, v, o);
    if (lane == 0) sw[wid] = v;
    __syncthreads();
    if (wid == 0) {
        int xx = sw[lane];
#pragma unroll
        for (int o = 16; o; o >>= 1) xx += __shfl_down_sync(0xffffffffu, xx, o);
        if (lane == 0) g_bsum[blockIdx.x] = xx;
    }
    __syncthreads();   // g_dis of this block's nodes visible to whole block
    // fused prescale: this block's 1024 nodes, coalesced (16 lanes per row)
    int base = blockIdx.x * 1024;
    for (int m = t; m < 1024 * 16; m += 1024) {
        int node = base + (m >> 4);
        if (node >= NN) break;
        int c = m & 15;
        float d = g_dis[node];
        float2 vx = ((const float2*)x)[(size_t)node * 16 + c];
        g_U0[(size_t)node * 16 + c] = __floats2half2_rn(d * vx.x, d * vx.y);
    }
}

// Scan stage C: block-local exclusive scan + base from preceding block sums.
__global__ void k_scanC() {
    __shared__ int s_ws[32];
    __shared__ int s_base;
    int b = blockIdx.x, t = threadIdx.x, lane = t & 31, wid = t >> 5;
    if (wid == 0) {
        int v = 0;
        if (lane < b)      v  = g_bsum[lane];
        if (lane + 32 < b) v += g_bsum[lane + 32];
#pragma unroll
        for (int o = 16; o; o >>= 1) v += __shfl_down_sync(0xffffffffu, v, o);
        if (lane == 0) s_base = v;
    }
    int idx = b * 1024 + t;
    int cnt = (idx < NN) ? g_cnt[idx] : 0;
    int v = cnt;
#pragma unroll
    for (int o = 1; o < 32; o <<= 1) {
        int u = __shfl_up_sync(0xffffffffu, v, o);
        if (lane >= o) v += u;
    }
    if (lane == 31) s_ws[wid] = v;
    __syncthreads();
    if (wid == 0) {
        int w = s_ws[lane];
#pragma unroll
        for (int o = 1; o < 32; o <<= 1) {
            int u = __shfl_up_sync(0xffffffffu, w, o);
            if (lane >= o) w += u;
        }
        s_ws[lane] = w;
    }
    __syncthreads();
    int excl = v - cnt + (wid ? s_ws[wid - 1] : 0) + s_base;
    if (idx < NN) { g_off[idx] = excl; g_cur[idx] = excl; }
}

// Fill CSR: scatter the cached payload by col.
__global__ void k_fill() {
    int e = blockIdx.x * blockDim.x + threadIdx.x;
    if (e >= EE) return;
    uint2 p = g_rcw[e];
    int pos = atomicAdd(&g_cur[p.y], 1);
    g_edgeP[pos] = p.x;
}

// Pull-mode fp16 spmm on rescaled basis (UNCHANGED from round 16 — passing):
//   Uout[c] = alpha * d2[c] * sum_e w[e]*Uin[src] + beta * Uprev[c]
__global__ void k_spmm16(const __half2* __restrict__ Tin, const __half2* __restrict__ Tprev,
                         __half2* __restrict__ Tout, float alpha, float beta)
{
    int gw = (blockIdx.x * blockDim.x + threadIdx.x) >> 5;
    if (gw >= NN) return;
    int lane = threadIdx.x & 31;
    int q = lane >> 3, l8 = lane & 7;
    const uint2* Tin8 = (const uint2*)Tin;   // row = 8 x uint2 (64B)
    int s = g_off[gw], e = g_off[gw + 1];
    float am = alpha * g_d2[gw];
    float2 acc0 = make_float2(0.f, 0.f);
    float2 acc1 = make_float2(0.f, 0.f);
    int j = s;
    int mis = j & 3;                          // peel to 4-alignment
    if (mis) {
        int cntp = 4 - mis; if (cntp > e - j) cntp = e - j;
        unsigned p = (q < cntp) ? __ldg(&g_edgeP[j + q]) : 0u;
        int s0 = p & 0xFFFFu;
        uint2 r0 = __ldg(&Tin8[(size_t)s0 * 8 + l8]);
        float w0 = wof(p);
        acc0 = ffma2(w0, __half22float2(*(const __half2*)&r0.x), acc0);
        acc1 = ffma2(w0, __half22float2(*(const __half2*)&r0.y), acc1);
        j += cntp;
    }
    for (; j + 16 <= e; j += 16) {
        uint4 ep = __ldg((const uint4*)g_edgeP + (j >> 2) + q);
        int s0 = ep.x & 0xFFFFu, s1 = ep.y & 0xFFFFu;
        int s2 = ep.z & 0xFFFFu, s3 = ep.w & 0xFFFFu;
        uint2 r0 = __ldg(&Tin8[(size_t)s0 * 8 + l8]);
        uint2 r1 = __ldg(&Tin8[(size_t)s1 * 8 + l8]);
        uint2 r2 = __ldg(&Tin8[(size_t)s2 * 8 + l8]);
        uint2 r3 = __ldg(&Tin8[(size_t)s3 * 8 + l8]);
        float w0 = wof(ep.x), w1 = wof(ep.y), w2 = wof(ep.z), w3 = wof(ep.w);
        acc0 = ffma2(w0, __half22float2(*(const __half2*)&r0.x), acc0);
        acc1 = ffma2(w0, __half22float2(*(const __half2*)&r0.y), acc1);
        acc0 = ffma2(w1, __half22float2(*(const __half2*)&r1.x), acc0);
        acc1 = ffma2(w1, __half22float2(*(const __half2*)&r1.y), acc1);
        acc0 = ffma2(w2, __half22float2(*(const __half2*)&r2.x), acc0);
        acc1 = ffma2(w2, __half22float2(*(const __half2*)&r2.y), acc1);
        acc0 = ffma2(w3, __half22float2(*(const __half2*)&r3.x), acc0);
        acc1 = ffma2(w3, __half22float2(*(const __half2*)&r3.y), acc1);
    }
    if (j + 8 <= e) {
        uint2 ep = __ldg((const uint2*)g_edgeP + (j >> 1) + q);
        int s0 = ep.x & 0xFFFFu, s1 = ep.y & 0xFFFFu;
        uint2 r0 = __ldg(&Tin8[(size_t)s0 * 8 + l8]);
        uint2 r1 = __ldg(&Tin8[(size_t)s1 * 8 + l8]);
        float w0 = wof(ep.x), w1 = wof(ep.y);
        acc0 = ffma2(w0, __half22float2(*(const __half2*)&r0.x), acc0);
        acc1 = ffma2(w0, __half22float2(*(const __half2*)&r0.y), acc1);
        acc0 = ffma2(w1, __half22float2(*(const __half2*)&r1.x), acc0);
        acc1 = ffma2(w1, __half22float2(*(const __half2*)&r1.y), acc1);
        j += 8;
    }
    for (; j < e; j += 4) {
        int idx = j + q;
        unsigned p = (idx < e) ? __ldg(&g_edgeP[idx]) : 0u;
        int s0 = p & 0xFFFFu;
        uint2 r0 = __ldg(&Tin8[(size_t)s0 * 8 + l8]);
        float w0 = wof(p);
        acc0 = ffma2(w0, __half22float2(*(const __half2*)&r0.x), acc0);
        acc1 = ffma2(w0, __half22float2(*(const __half2*)&r0.y), acc1);
    }
#pragma unroll
    for (int o = 8; o <= 16; o <<= 1) {
        acc0.x += __shfl_xor_sync(0xffffffffu, acc0.x, o);
        acc0.y += __shfl_xor_sync(0xffffffffu, acc0.y, o);
        acc1.x += __shfl_xor_sync(0xffffffffu, acc1.x, o);
        acc1.y += __shfl_xor_sync(0xffffffffu, acc1.y, o);
    }
    if (lane < 8) {
        float2 r0 = make_float2(am * acc0.x, am * acc0.y);
        float2 r1 = make_float2(am * acc1.x, am * acc1.y);
        if (beta != 0.f) {
            uint2 tp = ((const uint2*)Tprev)[(size_t)gw * 8 + lane];
            float2 t0 = __half22float2(*(const __half2*)&tp.x);
            float2 t1 = __half22float2(*(const __half2*)&tp.y);
            r0 = ffma2(beta, t0, r0);
            r1 = ffma2(beta, t1, r1);
        }
        uint2 o2;
        *(__half2*)&o2.x = __floats2half2_rn(r0.x, r0.y);
        *(__half2*)&o2.y = __floats2half2_rn(r1.x, r1.y);
        ((uint2*)Tout)[(size_t)gw * 8 + lane] = o2;
    }
}

// H = 0 GRU path: relu((1 - sigmoid(z)) * tanh(h)), MUFU-based fast math
__device__ __forceinline__ float gruact(float z, float h) {
    float sg = __fdividef(1.f, 1.f + __expf(-z));            // sigmoid
    float th = 1.f - __fdividef(2.f, __expf(2.f * h) + 1.f); // tanh; inf-safe
    float v = (1.f - sg) * th;
    return fmaxf(v, 0.f);
}

// Cell-1 dense combine, REGISTER-BLOCKED: lane = node (group of 32 nodes/warp),
// two warps per group (j-halves 0..15 / 16..31). Weights broadcast from smem
// via LDS.128 (1 MIO op serving all 32 nodes) — no shfl in the inner loop.
// All 5 inputs are U_k (k=0 uses U0 = dis.*x): z = s[n]*acc + bias.
// Writes h1h = dis[n] * h1 (the cell-2 U0).
__global__ void __launch_bounds__(256) k_gemm1(
        const float* __restrict__ Wx1,
        const float* __restrict__ bx1, const float* __restrict__ bh1)
{
    __shared__ float2 sW[KCH * 32 * 32];    // 40KB: [k][i][j] -> {wz, wh}
    __shared__ float sbz[32], sbh[32];
    int tid = threadIdx.x;
    for (int i = tid; i < KCH * 32 * 32; i += 256)
        sW[i] = make_float2(Wx1[i], Wx1[2 * KCH * 32 * 32 + i]);  // gates 0 (z), 2 (h)
    if (tid < 32) {
        sbz[tid] = bx1[tid]      + bh1[tid];
        sbh[tid] = bx1[64 + tid] + bh1[64 + tid];
    }
    __syncthreads();
    int warp = tid >> 5, lane = tid & 31;
    int jh = warp & 1;
    int base = jh * 16;
    int slot = blockIdx.x * 4 + (warp >> 1);
    int totSlots = gridDim.x * 4;
    const uint4* const Us[5] = { (const uint4*)g_U0,  (const uint4*)g_T1h,
                                 (const uint4*)g_T2h, (const uint4*)g_T3h,
                                 (const uint4*)g_T4h };
    __half* h1 = (__half*)g_h1h;

    for (int grp = slot; grp * 32 < NN; grp += totSlots) {
        int n = grp * 32 + lane;
        bool valid = (n < NN);
        int nr = valid ? n : 0;
        float2 acc[16];
#pragma unroll
        for (int jj = 0; jj < 16; ++jj) acc[jj] = make_float2(0.f, 0.f);
#pragma unroll
        for (int k = 0; k < KCH; ++k) {
            const uint4* row = Us[k] + (size_t)nr * 4;
#pragma unroll
            for (int c = 0; c < 4; ++c) {
                uint4 rv = __ldg(row + c);
                float2 v01 = __half22float2(*(const __half2*)&rv.x);
                float2 v23 = __half22float2(*(const __half2*)&rv.y);
                float2 v45 = __half22float2(*(const __half2*)&rv.z);
                float2 v67 = __half22float2(*(const __half2*)&rv.w);
                float v[8] = { v01.x, v01.y, v23.x, v23.y,
                               v45.x, v45.y, v67.x, v67.y };
#pragma unroll
                for (int u = 0; u < 8; ++u) {
                    const float4* w4 =
                        (const float4*)&sW[(k * 32 + c * 8 + u) * 32 + base];
#pragma unroll
                    for (int p = 0; p < 8; ++p) {
                        float4 wp = w4[p];   // j = 2p, 2p+1
                        acc[2 * p]     = ffma2(v[u], make_float2(wp.x, wp.y), acc[2 * p]);
                        acc[2 * p + 1] = ffma2(v[u], make_float2(wp.z, wp.w), acc[2 * p + 1]);
                    }
                }
            }
        }
        if (valid) {
            float sn = g_s[n], dn = g_dis[n];
            __half hv[16];
#pragma unroll
            for (int jj = 0; jj < 16; ++jj) {
                float z = fmaf(sn, acc[jj].x, sbz[base + jj]);
                float h = fmaf(sn, acc[jj].y, sbh[base + jj]);
                hv[jj] = __float2half_rn(dn * gruact(z, h));
            }
            uint4* dst = (uint4*)(h1 + (size_t)n * 32 + base);
            dst[0] = *(const uint4*)&hv[0];
            dst[1] = *(const uint4*)&hv[8];
        }
    }
}

// Cell-2 dense combine + output projection, REGISTER-BLOCKED: lane = node,
// one warp per 32-node group (all 16 outputs in registers), fused h2->out proj.
__global__ void __launch_bounds__(256) k_gemm2(
        const float* __restrict__ Wx2, const float* __restrict__ bx2,
        const float* __restrict__ bh2, const float* __restrict__ Wl,
        const float* __restrict__ bl,  float* __restrict__ out)
{
    __shared__ float2 sW[KCH * 32 * 16];    // 10KB: [k][i][jj] -> {wz, wh}
    __shared__ float sbz[16], sbh[16], sWl[PD * 16], sbl2[PD];
    int tid = threadIdx.x;
    for (int i = tid; i < KCH * 32 * 16; i += 256)
        sW[i] = make_float2(Wx2[i], Wx2[2 * KCH * 32 * 16 + i]);
    if (tid < PD * H2D) sWl[tid] = Wl[tid];
    if (tid < 16) {
        sbz[tid] = bx2[tid]      + bh2[tid];
        sbh[tid] = bx2[32 + tid] + bh2[32 + tid];
    }
    if (tid >= 240 && tid < 240 + PD) sbl2[tid - 240] = bl[tid - 240];
    __syncthreads();
    int warp = tid >> 5, lane = tid & 31;
    int slot = blockIdx.x * 8 + warp;
    int totSlots = gridDim.x * 8;
    const uint4* const Us[5] = { (const uint4*)g_h1h, (const uint4*)g_T1h,
                                 (const uint4*)g_T2h, (const uint4*)g_T3h,
                                 (const uint4*)g_T4h };

    for (int grp = slot; grp * 32 < NN; grp += totSlots) {
        int n = grp * 32 + lane;
        bool valid = (n < NN);
        int nr = valid ? n : 0;
        float2 acc[16];
#pragma unroll
        for (int jj = 0; jj < 16; ++jj) acc[jj] = make_float2(0.f, 0.f);
#pragma unroll
        for (int k = 0; k < KCH; ++k) {
            const uint4* row = Us[k] + (size_t)nr * 4;
#pragma unroll
            for (int c = 0; c < 4; ++c) {
                uint4 rv = __ldg(row + c);
                float2 v01 = __half22float2(*(const __half2*)&rv.x);
                float2 v23 = __half22float2(*(const __half2*)&rv.y);
                float2 v45 = __half22float2(*(const __half2*)&rv.z);
                float2 v67 = __half22float2(*(const __half2*)&rv.w);
                float v[8] = { v01.x, v01.y, v23.x, v23.y,
                               v45.x, v45.y, v67.x, v67.y };
#pragma unroll
                for (int u = 0; u < 8; ++u) {
                    const float4* w4 =
                        (const float4*)&sW[(k * 32 + c * 8 + u) * 16];
#pragma unroll
                    for (int p = 0; p < 8; ++p) {
                        float4 wp = w4[p];
                        acc[2 * p]     = ffma2(v[u], make_float2(wp.x, wp.y), acc[2 * p]);
                        acc[2 * p + 1] = ffma2(v[u], make_float2(wp.z, wp.w), acc[2 * p + 1]);
                    }
                }
            }
        }
        if (valid) {
            float sn = g_s[n];
            float h2[16];
#pragma unroll
            for (int jj = 0; jj < 16; ++jj)
                h2[jj] = gruact(fmaf(sn, acc[jj].x, sbz[jj]),
                                fmaf(sn, acc[jj].y, sbh[jj]));
            float o[PD];
#pragma unroll
            for (int p = 0; p < PD; ++p) {
                const float4* wl4 = (const float4*)&sWl[p * 16];
                float s = sbl2[p];
#pragma unroll
                for (int qd = 0; qd < 4; ++qd) {
                    float4 wq = wl4[qd];
                    s = fmaf(h2[4 * qd + 0], wq.x,
                        fmaf(h2[4 * qd + 1], wq.y,
                        fmaf(h2[4 * qd + 2], wq.z,
                        fmaf(h2[4 * qd + 3], wq.w, s))));
                }
                o[p] = s;
            }
            float4* dst = (float4*)(out + (size_t)n * PD);   // 48B, 16B-aligned
            dst[0] = make_float4(o[0], o[1], o[2],  o[3]);
            dst[1] = make_float4(o[4], o[5], o[6],  o[7]);
            dst[2] = make_float4(o[8], o[9], o[10], o[11]);
        }
    }
}

// -------------------------------- launch --------------------------------
extern "C" void kernel_launch(void* const* d_in, const int* in_sizes, int n_in,
                              void* d_out, int out_size)
{
    const float* x   = (const float*)d_in[0];
    const int*   ei  = (const int*)  d_in[1];   // int32 view; dtype auto-detected
    const float* ew  = (const float*)d_in[2];
    const float* Wx1 = (const float*)d_in[3];
    const float* bx1 = (const float*)d_in[4];
    // d_in[5] = Wh1: dead (H=0)
    const float* bh1 = (const float*)d_in[6];
    const float* Wx2 = (const float*)d_in[7];
    const float* bx2 = (const float*)d_in[8];
    // d_in[9] = Wh2: dead (H=0)
    const float* bh2 = (const float*)d_in[10];
    const float* Wl  = (const float*)d_in[11];
    const float* bl  = (const float*)d_in[12];
    float* out = (float*)d_out;

    __half2 *U0, *T1p, *T2p, *T3p, *T4p, *h1p;
    cudaGetSymbolAddress((void**)&U0,  g_U0);
    cudaGetSymbolAddress((void**)&T1p, g_T1h);
    cudaGetSymbolAddress((void**)&T2p, g_T2h);
    cudaGetSymbolAddress((void**)&T3p, g_T3h);
    cudaGetSymbolAddress((void**)&T4p, g_T4h);
    cudaGetSymbolAddress((void**)&h1p, g_h1h);

    const int EB = (EE + 255) / 256;
    const int SB = (NN * 32 + 255) / 256;  // warp-per-node spmm

    // CSR build + rescaled basis prep (prescale fused into scanA)
    k_init<<<(NN + 255) / 256, 256>>>(ei);
    k_conv<<<EB, 256>>>(ei, ew);
    k_scanA<<<NB, 1024>>>(x);
    k_scanC<<<NB, 1024>>>();
    k_fill<<<EB, 256>>>();

    // Cell 1: Chebyshev U1..U4 on U0 = dis.*x, then fused gate GEMM + act -> h1
    k_spmm16<<<SB, 256>>>(U0,  U0,  T1p, -1.f,  0.f);
    k_spmm16<<<SB, 256>>>(T1p, U0,  T2p, -2.f, -1.f);
    k_spmm16<<<SB, 256>>>(T2p, T1p, T3p, -2.f, -1.f);
    k_spmm16<<<SB, 256>>>(T3p, T2p, T4p, -2.f, -1.f);
    k_gemm1<<<GB1, 256>>>(Wx1, bx1, bh1);

    // Cell 2: Chebyshev on U0' = dis.*h1, fused gate GEMM + act + output proj
    k_spmm16<<<SB, 256>>>(h1p, h1p, T1p, -1.f,  0.f);
    k_spmm16<<<SB, 256>>>(T1p, h1p, T2p, -2.f, -1.f);
    k_spmm16<<<SB, 256>>>(T2p, T1p, T3p, -2.f, -1.f);
    k_spmm16<<<SB, 256>>>(T3p, T2p, T4p, -2.f, -1.f);
    k_gemm2<<<GB2, 256>>>(Wx2, bx2, bh2, Wl, bl, out);
}